// round 16
// baseline (speedup 1.0000x reference)
#include <cuda_runtime.h>
#include <math.h>
#include <stdint.h>

// Problem constants
#define BGRAPH   256
#define M_ATOMS  48
#define NNODES   (BGRAPH * M_ATOMS)          // 12288
#define GRAPH_E  (M_ATOMS * (M_ATOMS - 1))   // 2256
#define EDGES    (BGRAPH * GRAPH_E)          // 577536
#define KRBF     32
#define NSH      25
#define FEAT     (KRBF + NSH)                // 57
#define HS       128
#define CUTOFF_INV (1.0f / 15.0f)

// Output layout (floats): feat [E,57] | node_emb [N,128] | edge_index [2,E] | transpose_index [E]
#define EMB_OFF  ((size_t)EDGES * FEAT)                 // 32,919,552
#define EI_OFF   (EMB_OFF + (size_t)NNODES * HS)        // 34,492,416
#define TR_OFF   (EI_OFF + 2 * (size_t)EDGES)           // 35,647,488

// 256-thread CTAs; edge blocks: warps 0-3 = p-side, warps 4-7 = q-side,
// both covering the same 128 edges (eloc = tid & 127).
#define EDGE_BLOCKS (EDGES / 128)                        // 4512
#define EMB_BLOCKS  ((NNODES * 32) / 256)                // 1536
#define TOTAL_BLOCKS (EDGE_BLOCKS + EMB_BLOCKS)          // 6048

// L2 residency: pin ~95 MB of the 145.8 MB output (R8-validated config).
#define PIN_FEAT_BLOCKS 2800

__device__ __forceinline__ uint32_t smem_u32(const void* p) {
    uint32_t a;
    asm("{ .reg .u64 t; cvta.to.shared.u64 t, %1; cvt.u32.u64 %0, t; }" : "=r"(a) : "l"(p));
    return a;
}
__device__ __forceinline__ uint64_t policy_evict_last() {
    uint64_t pol;
    asm("createpolicy.fractional.L2::evict_last.b64 %0, 1.0;" : "=l"(pol));
    return pol;
}
__device__ __forceinline__ uint64_t policy_evict_first() {
    uint64_t pol;
    asm("createpolicy.fractional.L2::evict_first.b64 %0, 1.0;" : "=l"(pol));
    return pol;
}
__device__ __forceinline__ void stg_hint(float* p, float v, uint64_t pol) {
    asm volatile("st.global.L2::cache_hint.f32 [%0], %1, %2;"
                 :: "l"(p), "f"(v), "l"(pol) : "memory");
}
__device__ __forceinline__ void stg4_hint(float4* p, float4 v, uint64_t pol) {
    asm volatile("st.global.L2::cache_hint.v4.f32 [%0], {%1,%2,%3,%4}, %5;"
                 :: "l"(p), "f"(v.x), "f"(v.y), "f"(v.z), "f"(v.w), "l"(pol) : "memory");
}

// ---------------------------------------------------------------------------
// Fused kernel: WARP-UNIFORM 2-way split per edge (no divergence).
//  blocks [0, 4512): 256 threads, 128 edges. Threads t and t+128 handle the
//    same edge. half = t>>7 is warp-uniform:
//      half 0: ascending Bernstein terms v=0..15 (from fcut*p^31, ratio q/p)
//              + sh[0..12] + edge_index stores
//      half 1: descending terms v=31..16 (from fcut*q^31, ratio p/q)
//              + sh[13..24] + transpose_index store
//    All smem store offsets are compile-time. One cp.async.bulk per block.
//  blocks [4512, 6048): embedding gather, 1 thread = 1 float4.
// ---------------------------------------------------------------------------
__global__ void __launch_bounds__(256) fused_kernel(
    const float*  __restrict__ pos,
    const int*    __restrict__ an,
    const float4* __restrict__ table4,
    const float*  __restrict__ alpha,
    float* __restrict__ out)
{
    __shared__ __align__(16) float tile[128 * FEAT];

    if (blockIdx.x >= EDGE_BLOCKS) {
        const int i = (blockIdx.x - EDGE_BLOCKS) * 256 + threadIdx.x; // < NNODES*32
        const int n = i >> 5;
        const int c = i & 31;
        float4* out4 = (float4*)(out + EMB_OFF);
        stg4_hint(out4 + i, table4[an[n] * 32 + c], policy_evict_last());
        return;
    }

    const int half = threadIdx.x >> 7;                 // warp-uniform!
    const int eloc = threadIdx.x & 127;                // edge within block
    const int e    = blockIdx.x * 128 + eloc;

    // ---- index math (duplicated across halves; cheap) ----
    const int g = e / GRAPH_E;
    const int t = e - g * GRAPH_E;
    const int s = t / (M_ATOMS - 1);
    const int k = t - s * (M_ATOMS - 1);
    const int d = k + (k >= s);
    const int src = g * M_ATOMS + s;
    const int dst = g * M_ATOMS + d;

    // ---- pos prefetch (coalesced-ish gather; both halves hit same lines) ----
    const float dx0 = __ldg(pos + dst * 3 + 0);
    const float dy0 = __ldg(pos + dst * 3 + 1);
    const float dz0 = __ldg(pos + dst * 3 + 2);
    const float sx0 = __ldg(pos + src * 3 + 0);
    const float sy0 = __ldg(pos + src * 3 + 1);
    const float sz0 = __ldg(pos + src * 3 + 2);

    // ---- index outputs, split warp-uniformly ----
    {
        const uint64_t pol = policy_evict_last();
        if (half == 0) {
            stg_hint(out + EI_OFF + e,         (float)dst, pol);
            stg_hint(out + EI_OFF + EDGES + e, (float)src, pol);
        } else {
            const int tr = g * GRAPH_E + d * (M_ATOMS - 1) + s - (d < s);
            stg_hint(out + TR_OFF + e, (float)tr, pol);
        }
    }

    // ---- geometry ----
    const float ex = dx0 - sx0, ey = dy0 - sy0, ez = dz0 - sz0;
    float r2 = fmaxf(ex * ex + ey * ey + ez * ez, 1e-12f);
    const float rinv = rsqrtf(r2);
    const float r    = r2 * rinv;
    const float x = ex * rinv, y = ey * rinv, z = ez * rinv;

    float* row = &tile[eloc * FEAT];

    // ---- cutoff (shared by both halves) ----
    const float rc  = r * CUTOFF_INV;
    const float rc2 = rc * rc;
    const float den = fmaxf((1.0f - rc) * (1.0f + rc), 1e-9f);
    const float fcut = (rc < 1.0f) ? __expf(-__fdividef(rc2, den)) : 0.0f;

    // ---- Bernstein basics (shared) ----
    const float aeff = 0.5f * alpha[0];
    const float p = __expf(-aeff * r);
    const float q = 1.0f - p;

    // ---- shared SH prefix ----
    const float C2 = x * x - y * y,      S2 = 2.0f * x * y;
    const float C3 = C2 * x - S2 * y,    S3 = S2 * x + C2 * y;
    const float z2 = z * z;
    float* sh = row + KRBF;

    if (half == 0) {
        // ====== ascending half: terms v = 0..15 from fcut * p^31 ======
        // (underflow of p^31 at large r is harmless: true terms negligible)
        const float rp  = __fdividef(q, p);
        const float rp2 = rp * rp;
        const float p2 = p * p, p4 = p2 * p2, p8 = p4 * p4, p16 = p8 * p8;
        float ev = p16 * p8 * p4 * p2 * p * fcut;    // term 0
        float ov = ev * (31.0f * rp);                // term 1
        row[0] = ev;
        row[1] = ov;
#pragma unroll
        for (int j = 0; j < 7; ++j) {
            const float ce = ((float)(31 - 2*j) * (float)(30 - 2*j)) /
                             ((float)(2*j + 1) * (float)(2*j + 2));
            const float co = ((float)(30 - 2*j) * (float)(29 - 2*j)) /
                             ((float)(2*j + 2) * (float)(2*j + 3));
            ev *= rp2 * ce;  row[2*j + 2] = ev;      // terms 2..14
            ov *= rp2 * co;  row[2*j + 3] = ov;      // terms 3..15
        }
        // sh[0..12]
        const float q20 = 1.5f  * z2 - 0.5f;
        const float q30 = (2.5f * z2 - 1.5f) * z;
        const float q31 = 7.5f  * z2 - 1.5f;
        sh[0]  = 1.0f;
        sh[1]  = 1.7320508f * y;
        sh[2]  = 1.7320508f * z;
        sh[3]  = 1.7320508f * x;
        sh[4]  = 1.9364917f * S2;
        sh[5]  = 3.8729833f * y * z;
        sh[6]  = 2.2360680f * q20;
        sh[7]  = 3.8729833f * x * z;
        sh[8]  = 1.9364917f * C2;
        sh[9]  = 2.0916500f * S3;
        sh[10] = 5.1234756f * z * S2;
        sh[11] = 1.0801234f * q31 * y;
        sh[12] = 2.6457513f * q30;
    } else {
        // ====== descending half: terms v = 31..16 from fcut * q^31 ======
        // term(31-u) = fcut * C(31,u) * q^31 * (p/q)^u  (binomial symmetry)
        const float rq  = __fdividef(p, q);
        const float rq2 = rq * rq;
        const float q2 = q * q, q4 = q2 * q2, q8 = q4 * q4, q16 = q8 * q8;
        float ev = q16 * q8 * q4 * q2 * q * fcut;    // term 31 (u=0)
        float ov = ev * (31.0f * rq);                // term 30 (u=1)
        row[31] = ev;
        row[30] = ov;
#pragma unroll
        for (int j = 0; j < 7; ++j) {
            const float ce = ((float)(31 - 2*j) * (float)(30 - 2*j)) /
                             ((float)(2*j + 1) * (float)(2*j + 2));
            const float co = ((float)(30 - 2*j) * (float)(29 - 2*j)) /
                             ((float)(2*j + 2) * (float)(2*j + 3));
            ev *= rq2 * ce;  row[31 - (2*j + 2)] = ev;   // terms 29..17
            ov *= rq2 * co;  row[31 - (2*j + 3)] = ov;   // terms 28..16
        }
        // sh[13..24]
        const float C4 = C3 * x - S3 * y,  S4 = S3 * x + C3 * y;
        const float q40 = (4.375f * z2 - 3.75f) * z2 + 0.375f;
        const float q31 = 7.5f  * z2 - 1.5f;
        const float q41 = (17.5f * z2 - 7.5f) * z;
        const float q42 = 52.5f * z2 - 7.5f;
        sh[13] = 1.0801234f * q31 * x;
        sh[14] = 5.1234756f * z * C2;
        sh[15] = 2.0916500f * C3;
        sh[16] = 2.2185299f * S4;
        sh[17] = 6.2749501f * z * S3;
        sh[18] = 0.2236068f * q42 * S2;
        sh[19] = 0.9486833f * q41 * y;
        sh[20] = 3.0f       * q40;
        sh[21] = 0.9486833f * q41 * x;
        sh[22] = 0.2236068f * q42 * C2;
        sh[23] = 6.2749501f * z * C3;
        sh[24] = 2.2185299f * C4;
    }

    // ---- flush block tile (29184 B, contiguous smem AND global) ----
    __syncthreads();
    if (threadIdx.x == 0) {
        asm volatile("fence.proxy.async.shared::cta;" ::: "memory");
        float* gdst = out + (size_t)blockIdx.x * (128 * FEAT);
        const uint32_t saddr = smem_u32(tile);
        const uint64_t pol = (blockIdx.x < PIN_FEAT_BLOCKS) ? policy_evict_last()
                                                            : policy_evict_first();
        asm volatile(
            "cp.async.bulk.global.shared::cta.bulk_group.L2::cache_hint [%0], [%1], %2, %3;"
            :: "l"(gdst), "r"(saddr), "r"(128 * FEAT * 4), "l"(pol) : "memory");
        asm volatile("cp.async.bulk.commit_group;" ::: "memory");
        asm volatile("cp.async.bulk.wait_group.read 0;" ::: "memory");
    }
}

extern "C" void kernel_launch(void* const* d_in, const int* in_sizes, int n_in,
                              void* d_out, int out_size)
{
    const float* pos   = (const float*)d_in[0];
    const int*   an    = (const int*)d_in[1];
    const float* table = (const float*)d_in[2];
    const float* alpha = (const float*)d_in[3];
    float* out = (float*)d_out;

    fused_kernel<<<TOTAL_BLOCKS, 256>>>(pos, an, (const float4*)table, alpha, out);
}

// round 17
// speedup vs baseline: 1.0509x; 1.0509x over previous
#include <cuda_runtime.h>
#include <math.h>
#include <stdint.h>

// Problem constants
#define BGRAPH   256
#define M_ATOMS  48
#define NNODES   (BGRAPH * M_ATOMS)          // 12288
#define GRAPH_E  (M_ATOMS * (M_ATOMS - 1))   // 2256
#define EDGES    (BGRAPH * GRAPH_E)          // 577536
#define KRBF     32
#define NSH      25
#define FEAT     (KRBF + NSH)                // 57
#define HS       128
#define CUTOFF_INV (1.0f / 15.0f)

// Output layout (floats): feat [E,57] | node_emb [N,128] | edge_index [2,E] | transpose_index [E]
#define EMB_OFF  ((size_t)EDGES * FEAT)                 // 32,919,552
#define EI_OFF   (EMB_OFF + (size_t)NNODES * HS)        // 34,492,416
#define TR_OFF   (EI_OFF + 2 * (size_t)EDGES)           // 35,647,488

// 256-thread CTAs; edge blocks: warps 0-3 = p-side, warps 4-7 = q-side,
// both covering the same 128 edges (eloc = tid & 127).
#define EDGE_BLOCKS (EDGES / 128)                        // 4512
#define EMB_BLOCKS  ((NNODES * 32) / 256)                // 1536
#define TOTAL_BLOCKS (EDGE_BLOCKS + EMB_BLOCKS)          // 6048

// L2 residency: pin ~83 MB (2400 * 29184 B = 70 MB feat + emb 6.3 + idx 6.9).
// Backed off from 2800 (R8 showed ~26 MB thrash at 95 MB pinned).
#define PIN_FEAT_BLOCKS 2400

__device__ __forceinline__ uint32_t smem_u32(const void* p) {
    uint32_t a;
    asm("{ .reg .u64 t; cvta.to.shared.u64 t, %1; cvt.u32.u64 %0, t; }" : "=r"(a) : "l"(p));
    return a;
}
__device__ __forceinline__ uint64_t policy_evict_last() {
    uint64_t pol;
    asm("createpolicy.fractional.L2::evict_last.b64 %0, 1.0;" : "=l"(pol));
    return pol;
}
__device__ __forceinline__ uint64_t policy_evict_first() {
    uint64_t pol;
    asm("createpolicy.fractional.L2::evict_first.b64 %0, 1.0;" : "=l"(pol));
    return pol;
}
__device__ __forceinline__ void stg_hint(float* p, float v, uint64_t pol) {
    asm volatile("st.global.L2::cache_hint.f32 [%0], %1, %2;"
                 :: "l"(p), "f"(v), "l"(pol) : "memory");
}
__device__ __forceinline__ void stg4_hint(float4* p, float4 v, uint64_t pol) {
    asm volatile("st.global.L2::cache_hint.v4.f32 [%0], {%1,%2,%3,%4}, %5;"
                 :: "l"(p), "f"(v.x), "f"(v.y), "f"(v.z), "f"(v.w), "l"(pol) : "memory");
}

// ---------------------------------------------------------------------------
// Fused kernel: warp-uniform 2-way split per edge + smem-staged pos.
//  blocks [0, 4512): 256 threads, 128 edges (threads t and t+128 share edge
//    t&127). A block's edges touch at most 2 graphs; their 2x144 pos floats
//    are staged into smem with ONE coalesced load, then read via
//    conflict-free LDS (stride-3 lanes / broadcast). half = t>>7:
//      half 0: ascending Bernstein v=0..15 (fcut*p^31, ratio q/p) + sh[0..12]
//      half 1: descending v=31..16 (fcut*q^31, ratio p/q) + sh[13..24]
//    One cp.async.bulk per block flushes the [128][57] tile.
//  blocks [4512, 6048): embedding gather, 1 thread = 1 float4.
// ---------------------------------------------------------------------------
__global__ void __launch_bounds__(256) fused_kernel(
    const float*  __restrict__ pos,
    const int*    __restrict__ an,
    const float4* __restrict__ table4,
    const float*  __restrict__ alpha,
    float* __restrict__ out)
{
    __shared__ __align__(16) float tile[128 * FEAT];
    __shared__ float posbuf[2][M_ATOMS * 3];            // 1152 B

    if (blockIdx.x >= EDGE_BLOCKS) {
        const int i = (blockIdx.x - EDGE_BLOCKS) * 256 + threadIdx.x; // < NNODES*32
        const int n = i >> 5;
        const int c = i & 31;
        float4* out4 = (float4*)(out + EMB_OFF);
        stg4_hint(out4 + i, table4[an[n] * 32 + c], policy_evict_last());
        return;
    }

    // ---- stage pos for the (at most) 2 graphs this block touches ----
    const int g0 = (blockIdx.x * 128) / GRAPH_E;
    const int g1 = (blockIdx.x * 128 + 127) / GRAPH_E;  // g0 or g0+1
    for (int i = threadIdx.x; i < 2 * M_ATOMS * 3; i += 256) {
        const int buf = (i >= M_ATOMS * 3);
        const int off = i - buf * (M_ATOMS * 3);
        posbuf[buf][off] = pos[(buf ? g1 : g0) * (M_ATOMS * 3) + off];
    }
    __syncthreads();

    const int half = threadIdx.x >> 7;                 // warp-uniform!
    const int eloc = threadIdx.x & 127;                // edge within block
    const int e    = blockIdx.x * 128 + eloc;

    // ---- index math ----
    const int g = e / GRAPH_E;
    const int t = e - g * GRAPH_E;
    const int s = t / (M_ATOMS - 1);
    const int k = t - s * (M_ATOMS - 1);
    const int d = k + (k >= s);
    const int src = g * M_ATOMS + s;
    const int dst = g * M_ATOMS + d;

    // ---- pos from smem: stride-3 lanes (conflict-free) / broadcast ----
    const float* pb = posbuf[g - g0];
    const float dx0 = pb[d * 3 + 0];
    const float dy0 = pb[d * 3 + 1];
    const float dz0 = pb[d * 3 + 2];
    const float sx0 = pb[s * 3 + 0];
    const float sy0 = pb[s * 3 + 1];
    const float sz0 = pb[s * 3 + 2];

    // ---- index outputs, split warp-uniformly ----
    {
        const uint64_t pol = policy_evict_last();
        if (half == 0) {
            stg_hint(out + EI_OFF + e,         (float)dst, pol);
            stg_hint(out + EI_OFF + EDGES + e, (float)src, pol);
        } else {
            const int tr = g * GRAPH_E + d * (M_ATOMS - 1) + s - (d < s);
            stg_hint(out + TR_OFF + e, (float)tr, pol);
        }
    }

    // ---- geometry ----
    const float ex = dx0 - sx0, ey = dy0 - sy0, ez = dz0 - sz0;
    float r2 = fmaxf(ex * ex + ey * ey + ez * ez, 1e-12f);
    const float rinv = rsqrtf(r2);
    const float r    = r2 * rinv;
    const float x = ex * rinv, y = ey * rinv, z = ez * rinv;

    float* row = &tile[eloc * FEAT];

    // ---- cutoff (shared by both halves) ----
    const float rc  = r * CUTOFF_INV;
    const float rc2 = rc * rc;
    const float den = fmaxf((1.0f - rc) * (1.0f + rc), 1e-9f);
    const float fcut = (rc < 1.0f) ? __expf(-__fdividef(rc2, den)) : 0.0f;

    // ---- Bernstein basics (shared) ----
    const float aeff = 0.5f * alpha[0];
    const float p = __expf(-aeff * r);
    const float q = 1.0f - p;

    // ---- shared SH prefix ----
    const float C2 = x * x - y * y,      S2 = 2.0f * x * y;
    const float C3 = C2 * x - S2 * y,    S3 = S2 * x + C2 * y;
    const float z2 = z * z;
    float* sh = row + KRBF;

    if (half == 0) {
        // ====== ascending half: terms v = 0..15 from fcut * p^31 ======
        const float rp  = __fdividef(q, p);
        const float rp2 = rp * rp;
        const float p2 = p * p, p4 = p2 * p2, p8 = p4 * p4, p16 = p8 * p8;
        float ev = p16 * p8 * p4 * p2 * p * fcut;    // term 0
        float ov = ev * (31.0f * rp);                // term 1
        row[0] = ev;
        row[1] = ov;
#pragma unroll
        for (int j = 0; j < 7; ++j) {
            const float ce = ((float)(31 - 2*j) * (float)(30 - 2*j)) /
                             ((float)(2*j + 1) * (float)(2*j + 2));
            const float co = ((float)(30 - 2*j) * (float)(29 - 2*j)) /
                             ((float)(2*j + 2) * (float)(2*j + 3));
            ev *= rp2 * ce;  row[2*j + 2] = ev;      // terms 2..14
            ov *= rp2 * co;  row[2*j + 3] = ov;      // terms 3..15
        }
        // sh[0..12]
        const float q20 = 1.5f  * z2 - 0.5f;
        const float q30 = (2.5f * z2 - 1.5f) * z;
        const float q31 = 7.5f  * z2 - 1.5f;
        sh[0]  = 1.0f;
        sh[1]  = 1.7320508f * y;
        sh[2]  = 1.7320508f * z;
        sh[3]  = 1.7320508f * x;
        sh[4]  = 1.9364917f * S2;
        sh[5]  = 3.8729833f * y * z;
        sh[6]  = 2.2360680f * q20;
        sh[7]  = 3.8729833f * x * z;
        sh[8]  = 1.9364917f * C2;
        sh[9]  = 2.0916500f * S3;
        sh[10] = 5.1234756f * z * S2;
        sh[11] = 1.0801234f * q31 * y;
        sh[12] = 2.6457513f * q30;
    } else {
        // ====== descending half: terms v = 31..16 from fcut * q^31 ======
        const float rq  = __fdividef(p, q);
        const float rq2 = rq * rq;
        const float q2 = q * q, q4 = q2 * q2, q8 = q4 * q4, q16 = q8 * q8;
        float ev = q16 * q8 * q4 * q2 * q * fcut;    // term 31 (u=0)
        float ov = ev * (31.0f * rq);                // term 30 (u=1)
        row[31] = ev;
        row[30] = ov;
#pragma unroll
        for (int j = 0; j < 7; ++j) {
            const float ce = ((float)(31 - 2*j) * (float)(30 - 2*j)) /
                             ((float)(2*j + 1) * (float)(2*j + 2));
            const float co = ((float)(30 - 2*j) * (float)(29 - 2*j)) /
                             ((float)(2*j + 2) * (float)(2*j + 3));
            ev *= rq2 * ce;  row[31 - (2*j + 2)] = ev;   // terms 29..17
            ov *= rq2 * co;  row[31 - (2*j + 3)] = ov;   // terms 28..16
        }
        // sh[13..24]
        const float C4 = C3 * x - S3 * y,  S4 = S3 * x + C3 * y;
        const float q40 = (4.375f * z2 - 3.75f) * z2 + 0.375f;
        const float q31 = 7.5f  * z2 - 1.5f;
        const float q41 = (17.5f * z2 - 7.5f) * z;
        const float q42 = 52.5f * z2 - 7.5f;
        sh[13] = 1.0801234f * q31 * x;
        sh[14] = 5.1234756f * z * C2;
        sh[15] = 2.0916500f * C3;
        sh[16] = 2.2185299f * S4;
        sh[17] = 6.2749501f * z * S3;
        sh[18] = 0.2236068f * q42 * S2;
        sh[19] = 0.9486833f * q41 * y;
        sh[20] = 3.0f       * q40;
        sh[21] = 0.9486833f * q41 * x;
        sh[22] = 0.2236068f * q42 * C2;
        sh[23] = 6.2749501f * z * C3;
        sh[24] = 2.2185299f * C4;
    }

    // ---- flush block tile (29184 B, contiguous smem AND global) ----
    __syncthreads();
    if (threadIdx.x == 0) {
        asm volatile("fence.proxy.async.shared::cta;" ::: "memory");
        float* gdst = out + (size_t)blockIdx.x * (128 * FEAT);
        const uint32_t saddr = smem_u32(tile);
        const uint64_t pol = (blockIdx.x < PIN_FEAT_BLOCKS) ? policy_evict_last()
                                                            : policy_evict_first();
        asm volatile(
            "cp.async.bulk.global.shared::cta.bulk_group.L2::cache_hint [%0], [%1], %2, %3;"
            :: "l"(gdst), "r"(saddr), "r"(128 * FEAT * 4), "l"(pol) : "memory");
        asm volatile("cp.async.bulk.commit_group;" ::: "memory");
        asm volatile("cp.async.bulk.wait_group.read 0;" ::: "memory");
    }
}

extern "C" void kernel_launch(void* const* d_in, const int* in_sizes, int n_in,
                              void* d_out, int out_size)
{
    const float* pos   = (const float*)d_in[0];
    const int*   an    = (const int*)d_in[1];
    const float* table = (const float*)d_in[2];
    const float* alpha = (const float*)d_in[3];
    float* out = (float*)d_out;

    fused_kernel<<<TOTAL_BLOCKS, 256>>>(pos, an, (const float4*)table, alpha, out);
}